// round 8
// baseline (speedup 1.0000x reference)
#include <cuda_runtime.h>
#include <cuda_bf16.h>

#define S_LEN 2048
#define B_DIM 32
#define H_DIM 1024
#define M_TOT (S_LEN * B_DIM)

// ---------------- scratch ----------------
__device__ __nv_bfloat16 g_w2_hi[H_DIM * H_DIM];
__device__ __nv_bfloat16 g_w2_lo[H_DIM * H_DIM];
__device__ float g_t1[B_DIM * H_DIM];
__device__ float g_scores[B_DIM * S_LEN];

// ---------------- helpers ----------------
__device__ __forceinline__ unsigned smem_u32(const void* p) {
    unsigned a;
    asm("{ .reg .u64 t; cvta.to.shared.u64 t, %1; cvt.u32.u64 %0, t; }" : "=r"(a) : "l"(p));
    return a;
}
__device__ __forceinline__ uint4 ldsm_x4(unsigned addr) {
    uint4 r;
    asm volatile("ldmatrix.sync.aligned.m8n8.x4.shared.b16 {%0,%1,%2,%3}, [%4];"
                 : "=r"(r.x), "=r"(r.y), "=r"(r.z), "=r"(r.w) : "r"(addr));
    return r;
}
__device__ __forceinline__ void mma_bf16(float* c, uint4 a, unsigned b0, unsigned b1) {
    asm volatile(
        "mma.sync.aligned.m16n8k16.row.col.f32.bf16.bf16.f32 "
        "{%0,%1,%2,%3}, {%4,%5,%6,%7}, {%8,%9}, {%0,%1,%2,%3};"
        : "+f"(c[0]), "+f"(c[1]), "+f"(c[2]), "+f"(c[3])
        : "r"(a.x), "r"(a.y), "r"(a.z), "r"(a.w), "r"(b0), "r"(b1));
}
__device__ __forceinline__ unsigned pack_bf16x2(float f0, float f1) {
    unsigned r;
    asm("cvt.rn.bf16x2.f32 %0, %1, %2;" : "=r"(r) : "f"(f1), "f"(f0));
    return r;
}
__device__ __forceinline__ void cp_async16(unsigned sdst, const void* gsrc) {
    unsigned long long g;
    asm("cvta.to.global.u64 %0, %1;" : "=l"(g) : "l"(gsrc));
    asm volatile("cp.async.cg.shared.global [%0], [%1], 16;" :: "r"(sdst), "l"(g) : "memory");
}
#define CP_COMMIT() asm volatile("cp.async.commit_group;" ::: "memory")
#define CP_WAIT0()  asm volatile("cp.async.wait_group 0;" ::: "memory")
#define CP_WAIT1()  asm volatile("cp.async.wait_group 1;" ::: "memory")

// rational tanh, 4 at a time, one Newton-refined RCP
__device__ __forceinline__ void tanh4(const float* x, float* y) {
    float al[4], be[4];
#pragma unroll
    for (int i = 0; i < 4; i++) {
        float xc = fminf(fmaxf(x[i], -7.90531110763549805f), 7.90531110763549805f);
        float t = xc * xc;
        float a = -2.76076847742355e-16f;
        a = fmaf(a, t, 2.00018790482477e-13f);
        a = fmaf(a, t, -8.60467152213735e-11f);
        a = fmaf(a, t, 5.12229709037114e-08f);
        a = fmaf(a, t, 1.48572235717979e-05f);
        a = fmaf(a, t, 6.37261928875436e-04f);
        a = fmaf(a, t, 4.89352455891786e-03f);
        al[i] = xc * a;
        float b = 1.19825839466702e-06f;
        b = fmaf(b, t, 1.18534705686654e-04f);
        b = fmaf(b, t, 2.26843463243900e-03f);
        be[i] = fmaf(b, t, 4.89352518554385e-03f);
    }
    float p01 = be[0] * be[1];
    float p23 = be[2] * be[3];
    float p = p01 * p23;
    float r;
    asm("rcp.approx.f32 %0, %1;" : "=f"(r) : "f"(p));
    r = r * fmaf(-p, r, 2.0f);
    float q01 = r * p23, q23 = r * p01;
    y[0] = al[0] * (q01 * be[1]);
    y[1] = al[1] * (q01 * be[0]);
    y[2] = al[2] * (q23 * be[3]);
    y[3] = al[3] * (q23 * be[2]);
}

// ---------------- prep: w2 split + t1 + init ----------------
#define PREP_W2_BLKS    1024
#define PREP_T1_BLKS    4096
#define PREP_INIT_BLKS  256
#define PREP_GRID (PREP_W2_BLKS + PREP_T1_BLKS + PREP_INIT_BLKS)

__global__ void k_prep(const float* __restrict__ attn_w,
                       const float* __restrict__ attn_b,
                       const float* __restrict__ hidden,
                       float* __restrict__ ctx) {
    int blk = blockIdx.x;
    int tid = threadIdx.x;
    if (blk < PREP_W2_BLKS) {
        int i = blk * 256 + tid;
        int row = i >> 8, c4 = i & 255;
        float4 x = *(const float4*)(attn_w + (size_t)row * (2 * H_DIM) + H_DIM + c4 * 4);
        float hx = __bfloat162float(__float2bfloat16(x.x));
        float hy = __bfloat162float(__float2bfloat16(x.y));
        float hz = __bfloat162float(__float2bfloat16(x.z));
        float hw = __bfloat162float(__float2bfloat16(x.w));
        ((uint2*)g_w2_hi)[i] = make_uint2(pack_bf16x2(x.x, x.y), pack_bf16x2(x.z, x.w));
        ((uint2*)g_w2_lo)[i] = make_uint2(pack_bf16x2(x.x - hx, x.y - hy),
                                          pack_bf16x2(x.z - hz, x.w - hw));
    } else if (blk < PREP_W2_BLKS + PREP_T1_BLKS) {
        int w = (blk - PREP_W2_BLKS) * 8 + (tid >> 5);
        int lane = tid & 31;
        int b = w >> 10;
        int h = w & (H_DIM - 1);
        const float4* hp = (const float4*)(hidden + (size_t)b * H_DIM);
        const float4* wp = (const float4*)(attn_w + (size_t)h * 2 * H_DIM);
        float acc = 0.f;
#pragma unroll
        for (int i = 0; i < 8; i++) {
            int idx = i * 32 + lane;
            float4 hv = hp[idx];
            float4 wv = wp[idx];
            acc += hv.x * wv.x + hv.y * wv.y + hv.z * wv.z + hv.w * wv.w;
        }
#pragma unroll
        for (int off = 16; off; off >>= 1) acc += __shfl_down_sync(0xffffffffu, acc, off);
        if (lane == 0) g_t1[w] = acc + attn_b[h];
    } else {
        int i = (blk - PREP_W2_BLKS - PREP_T1_BLKS) * 256 + tid;
        if (i < B_DIM * S_LEN) g_scores[i] = 0.f;
        if (i < B_DIM * H_DIM) ctx[i] = 0.f;
    }
}

// ---------------- K1: 128x128 CTA (4 warps), 2 CTAs/SM, in-loop A split ----------------
#define BM 128
#define BN 128
#define BK 32
#define A_HI 0
#define A_LO 8192
#define B_HI 16384
#define B_LO 24576
#define STAGE_B 32768
#define NSTAGE 3
#define VS_OFF  (NSTAGE * STAGE_B)          // 98304: 128 f32
#define SROW_OFF (VS_OFF + 512)             // 98816: 128 f32
#define K1_SMEM  (SROW_OFF + 512)           // 99328

__device__ __forceinline__ unsigned sw_off(int row, int c16) {
    return (unsigned)row * 64u + (unsigned)((c16 ^ ((row >> 1) & 3)) << 4);
}

// B fill via cp.async (bf16 pre-split w2)
__device__ __forceinline__ void cpa_b(unsigned sb, int n0, int kk, int tid) {
#pragma unroll
    for (int i = 0; i < 4; i++) {
        int idx = i * 128 + tid;
        int row = idx >> 2, c16 = idx & 3;
        size_t goff = (size_t)(n0 + row) * H_DIM + kk + c16 * 8;
        unsigned soff = sw_off(row, c16);
        cp_async16(sb + B_HI + soff, g_w2_hi + goff);
        cp_async16(sb + B_LO + soff, g_w2_lo + goff);
    }
}

// A: load 4 float4 (half a tile) from fp32 enc
__device__ __forceinline__ void ldg_a4(float4* r, const float* enc, int m0, int kk,
                                       int tid, int i0) {
#pragma unroll
    for (int i = 0; i < 4; i++) {
        int idx = (i0 + i) * 128 + tid;
        int row = idx >> 3, c4 = idx & 7;
        r[i] = *(const float4*)(enc + (size_t)(m0 + row) * H_DIM + kk + c4 * 4);
    }
}
// A: convert + store 4 float4 worth of hi/lo bf16
__device__ __forceinline__ void sts_a4(const float4* r, char* sbp, int tid, int i0) {
#pragma unroll
    for (int i = 0; i < 4; i++) {
        int idx = (i0 + i) * 128 + tid;
        int row = idx >> 3, c4 = idx & 7;
        float4 x = r[i];
        float hx = __bfloat162float(__float2bfloat16(x.x));
        float hy = __bfloat162float(__float2bfloat16(x.y));
        float hz = __bfloat162float(__float2bfloat16(x.z));
        float hw = __bfloat162float(__float2bfloat16(x.w));
        uint2 hi = make_uint2(pack_bf16x2(x.x, x.y), pack_bf16x2(x.z, x.w));
        uint2 lo = make_uint2(pack_bf16x2(x.x - hx, x.y - hy), pack_bf16x2(x.z - hz, x.w - hw));
        unsigned soff = sw_off(row, c4 >> 1) + (unsigned)(c4 & 1) * 8u;
        *(uint2*)(sbp + A_HI + soff) = hi;
        *(uint2*)(sbp + A_LO + soff) = lo;
    }
}

__global__ void __launch_bounds__(128, 2) k1_gemm(const float* __restrict__ enc,
                                                  const float* __restrict__ v) {
    extern __shared__ char smem[];
    const unsigned sbase = smem_u32(smem);
    const int tid = threadIdx.x;
    const int L = tid & 31;
    const int wm = (tid >> 5) & 1;
    const int wn = tid >> 6;
    const int m0 = blockIdx.y * BM;
    const int n0 = blockIdx.x * BN;

    // prologue: A tiles 0,1 via LDG+STS; B tiles 0,1 via cp.async
    {
        float4 ra[4];
        cpa_b(sbase, n0, 0, tid);
        CP_COMMIT();
        cpa_b(sbase + STAGE_B, n0, BK, tid);
        CP_COMMIT();
        ldg_a4(ra, enc, m0, 0, tid, 0);
        sts_a4(ra, smem, tid, 0);
        ldg_a4(ra, enc, m0, 0, tid, 4);
        sts_a4(ra, smem, tid, 4);
        ldg_a4(ra, enc, m0, BK, tid, 0);
        sts_a4(ra, smem + STAGE_B, tid, 0);
        ldg_a4(ra, enc, m0, BK, tid, 4);
        sts_a4(ra, smem + STAGE_B, tid, 4);
    }

    float* vs = (float*)(smem + VS_OFF);
    float* srow = (float*)(smem + SROW_OFF);
    vs[tid] = v[n0 + tid];
    srow[tid] = 0.f;

    float acc[4][8][4];
#pragma unroll
    for (int i = 0; i < 4; i++)
#pragma unroll
        for (int j = 0; j < 8; j++)
#pragma unroll
            for (int e = 0; e < 4; e++) acc[i][j][e] = 0.f;

    const int a_r = wm * 64 + ((L >> 3) & 1) * 8 + (L & 7);
    const int a_c = (L >> 4);
    const int b_r = wn * 64 + (L >> 4) * 8 + (L & 7);
    const int b_c = ((L >> 3) & 1);

    const int NKT = H_DIM / BK;              // 32
    int slot = 0, nslot = 2;
    for (int kt = 0; kt < NKT; kt++) {
        if (kt + 1 < NKT) { CP_WAIT1(); } else { CP_WAIT0(); }
        __syncthreads();
        const bool pf = (kt + 2 < NKT);
        char* nsb = smem + nslot * STAGE_B;
        float4 ra[4];
        if (pf) {
            ldg_a4(ra, enc, m0, (kt + 2) * BK, tid, 0);
            cpa_b(sbase + nslot * STAGE_B, n0, (kt + 2) * BK, tid);
            CP_COMMIT();
        }
        const unsigned sb = sbase + slot * STAGE_B;

        // ---- ks = 0 ----
        {
            uint4 ah[4], al[4], bh[4], bl[4];
#pragma unroll
            for (int mf = 0; mf < 4; mf++) {
                unsigned off = sw_off(a_r + mf * 16, a_c);
                ah[mf] = ldsm_x4(sb + A_HI + off);
                al[mf] = ldsm_x4(sb + A_LO + off);
            }
#pragma unroll
            for (int nf2 = 0; nf2 < 4; nf2++) {
                unsigned off = sw_off(b_r + nf2 * 16, b_c);
                bh[nf2] = ldsm_x4(sb + B_HI + off);
                bl[nf2] = ldsm_x4(sb + B_LO + off);
            }
#pragma unroll
            for (int mf = 0; mf < 4; mf++)
#pragma unroll
                for (int nf2 = 0; nf2 < 4; nf2++) {
                    mma_bf16(acc[mf][nf2 * 2],     ah[mf], bh[nf2].x, bh[nf2].y);
                    mma_bf16(acc[mf][nf2 * 2 + 1], ah[mf], bh[nf2].z, bh[nf2].w);
                }
#pragma unroll
            for (int mf = 0; mf < 4; mf++)
#pragma unroll
                for (int nf2 = 0; nf2 < 4; nf2++) {
                    mma_bf16(acc[mf][nf2 * 2],     ah[mf], bl[nf2].x, bl[nf2].y);
                    mma_bf16(acc[mf][nf2 * 2 + 1], ah[mf], bl[nf2].z, bl[nf2].w);
                }
#pragma unroll
            for (int mf = 0; mf < 4; mf++)
#pragma unroll
                for (int nf2 = 0; nf2 < 4; nf2++) {
                    mma_bf16(acc[mf][nf2 * 2],     al[mf], bh[nf2].x, bh[nf2].y);
                    mma_bf16(acc[mf][nf2 * 2 + 1], al[mf], bh[nf2].z, bh[nf2].w);
                }
        }
        if (pf) {
            sts_a4(ra, nsb, tid, 0);
            ldg_a4(ra, enc, m0, (kt + 2) * BK, tid, 4);
        }
        // ---- ks = 1 ----
        {
            uint4 ah[4], al[4], bh[4], bl[4];
#pragma unroll
            for (int mf = 0; mf < 4; mf++) {
                unsigned off = sw_off(a_r + mf * 16, 2 + a_c);
                ah[mf] = ldsm_x4(sb + A_HI + off);
                al[mf] = ldsm_x4(sb + A_LO + off);
            }
#pragma unroll
            for (int nf2 = 0; nf2 < 4; nf2++) {
                unsigned off = sw_off(b_r + nf2 * 16, 2 + b_c);
                bh[nf2] = ldsm_x4(sb + B_HI + off);
                bl[nf2] = ldsm_x4(sb + B_LO + off);
            }
#pragma unroll
            for (int mf = 0; mf < 4; mf++)
#pragma unroll
                for (int nf2 = 0; nf2 < 4; nf2++) {
                    mma_bf16(acc[mf][nf2 * 2],     ah[mf], bh[nf2].x, bh[nf2].y);
                    mma_bf16(acc[mf][nf2 * 2 + 1], ah[mf], bh[nf2].z, bh[nf2].w);
                }
#pragma unroll
            for (int mf = 0; mf < 4; mf++)
#pragma unroll
                for (int nf2 = 0; nf2 < 4; nf2++) {
                    mma_bf16(acc[mf][nf2 * 2],     ah[mf], bl[nf2].x, bl[nf2].y);
                    mma_bf16(acc[mf][nf2 * 2 + 1], ah[mf], bl[nf2].z, bl[nf2].w);
                }
#pragma unroll
            for (int mf = 0; mf < 4; mf++)
#pragma unroll
                for (int nf2 = 0; nf2 < 4; nf2++) {
                    mma_bf16(acc[mf][nf2 * 2],     al[mf], bh[nf2].x, bh[nf2].y);
                    mma_bf16(acc[mf][nf2 * 2 + 1], al[mf], bh[nf2].z, bh[nf2].w);
                }
        }
        if (pf) sts_a4(ra, nsb, tid, 4);

        slot = (slot == 2) ? 0 : slot + 1;
        nslot = (nslot == 2) ? 0 : nslot + 1;
    }

    // ---------------- epilogue: batched t1 loads + tanh + v-dot + row reduce ----------------
    const int q = L >> 2;
#pragma unroll
    for (int mf = 0; mf < 4; mf++) {
        const int r0 = m0 + wm * 64 + mf * 16 + q;
        const int bb0 = r0 & 31;
        const int bb1 = (r0 + 8) & 31;
        float2 t0a[8], t1a[8];
#pragma unroll
        for (int nf = 0; nf < 8; nf++) {
            const int c = n0 + wn * 64 + nf * 8 + (L & 3) * 2;
            t0a[nf] = __ldg((const float2*)(g_t1 + (size_t)bb0 * H_DIM + c));
            t1a[nf] = __ldg((const float2*)(g_t1 + (size_t)bb1 * H_DIM + c));
        }
        float rp0 = 0.f, rp1 = 0.f;
#pragma unroll
        for (int nf = 0; nf < 8; nf++) {
            const int cl = wn * 64 + nf * 8 + (L & 3) * 2;
            float x[4], y[4];
            x[0] = acc[mf][nf][0] + t0a[nf].x;
            x[1] = acc[mf][nf][1] + t0a[nf].y;
            x[2] = acc[mf][nf][2] + t1a[nf].x;
            x[3] = acc[mf][nf][3] + t1a[nf].y;
            tanh4(x, y);
            rp0 += y[0] * vs[cl] + y[1] * vs[cl + 1];
            rp1 += y[2] * vs[cl] + y[3] * vs[cl + 1];
        }
        rp0 += __shfl_xor_sync(0xffffffffu, rp0, 1);
        rp0 += __shfl_xor_sync(0xffffffffu, rp0, 2);
        rp1 += __shfl_xor_sync(0xffffffffu, rp1, 1);
        rp1 += __shfl_xor_sync(0xffffffffu, rp1, 2);
        if ((L & 3) == 0) {
            atomicAdd(&srow[wm * 64 + mf * 16 + q], rp0);
            atomicAdd(&srow[wm * 64 + mf * 16 + q + 8], rp1);
        }
    }
    __syncthreads();
    {
        int rowg = m0 + tid;
        atomicAdd(&g_scores[(rowg & 31) * S_LEN + (rowg >> 5)], srow[tid]);
    }
}

// ---------------- softmax ----------------
__global__ void k2_softmax(const int* __restrict__ lens, float* __restrict__ wout) {
    __shared__ float red[256];
    int b = blockIdx.x;
    int len = lens[b];
    const float* sc = g_scores + (size_t)b * S_LEN;
    int tid = threadIdx.x;

    float mx = -3.4e38f;
    for (int s = tid; s < len; s += 256) mx = fmaxf(mx, sc[s]);
    red[tid] = mx;
    __syncthreads();
    for (int off = 128; off; off >>= 1) {
        if (tid < off) red[tid] = fmaxf(red[tid], red[tid + off]);
        __syncthreads();
    }
    mx = red[0];
    __syncthreads();

    float sum = 0.f;
    for (int s = tid; s < len; s += 256) sum += expf(sc[s] - mx);
    red[tid] = sum;
    __syncthreads();
    for (int off = 128; off; off >>= 1) {
        if (tid < off) red[tid] += red[tid + off];
        __syncthreads();
    }
    float inv = 1.f / red[0];

    for (int s = tid; s < S_LEN; s += 256)
        wout[(size_t)b * S_LEN + s] = (s < len) ? expf(sc[s] - mx) * inv : 0.f;
}

// ---------------- context ----------------
#define NCHUNK 64
__global__ void k3_context(const float* __restrict__ enc,
                           const float* __restrict__ wts,
                           const int* __restrict__ lens,
                           float* __restrict__ ctx) {
    int b = blockIdx.y;
    int len = lens[b];
    int s0 = blockIdx.x * (S_LEN / NCHUNK);
    int s1 = min(s0 + (S_LEN / NCHUNK), len);
    if (s0 >= s1) return;
    int h = threadIdx.x * 4;
    float4 acc = make_float4(0.f, 0.f, 0.f, 0.f);
    for (int s = s0; s < s1; s++) {
        float w = __ldg(&wts[(size_t)b * S_LEN + s]);
        float4 e = *(const float4*)(enc + ((size_t)(s * B_DIM + b)) * H_DIM + h);
        acc.x += w * e.x; acc.y += w * e.y; acc.z += w * e.z; acc.w += w * e.w;
    }
    float* c = ctx + (size_t)b * H_DIM + h;
    atomicAdd(c + 0, acc.x);
    atomicAdd(c + 1, acc.y);
    atomicAdd(c + 2, acc.z);
    atomicAdd(c + 3, acc.w);
}

// ---------------- launcher ----------------
extern "C" void kernel_launch(void* const* d_in, const int* in_sizes, int n_in,
                              void* d_out, int out_size) {
    const float* hidden = (const float*)d_in[0];
    const float* enc    = (const float*)d_in[1];
    const int*   lens   = (const int*)d_in[2];
    const float* attn_w = (const float*)d_in[3];
    const float* attn_b = (const float*)d_in[4];
    const float* v      = (const float*)d_in[5];

    float* out = (float*)d_out;
    float* ctx = out;
    float* wts = out + B_DIM * H_DIM;

    cudaFuncSetAttribute(k1_gemm, cudaFuncAttributeMaxDynamicSharedMemorySize, K1_SMEM);

    k_prep<<<PREP_GRID, 256>>>(attn_w, attn_b, hidden, ctx);
    dim3 g1(H_DIM / BN, M_TOT / BM);     // (8, 512), n fastest -> A reuse in L2
    k1_gemm<<<g1, 128, K1_SMEM>>>(enc, v);
    k2_softmax<<<B_DIM, 256>>>(lens, wts);
    dim3 g3(NCHUNK, B_DIM);
    k3_context<<<g3, 256>>>(enc, wts, lens, ctx);
}

// round 9
// speedup vs baseline: 1.0417x; 1.0417x over previous
#include <cuda_runtime.h>
#include <cuda_bf16.h>

#define S_LEN 2048
#define B_DIM 32
#define H_DIM 1024
#define M_TOT (S_LEN * B_DIM)

// ---------------- scratch ----------------
__device__ __nv_bfloat16 g_enc_hi[(size_t)M_TOT * H_DIM];   // 128 MB
__device__ __nv_bfloat16 g_enc_lo[(size_t)M_TOT * H_DIM];   // 128 MB
__device__ __nv_bfloat16 g_w2_hi[H_DIM * H_DIM];
__device__ __nv_bfloat16 g_w2_lo[H_DIM * H_DIM];
__device__ float g_t1[B_DIM * H_DIM];
__device__ float g_scores[B_DIM * S_LEN];

// ---------------- helpers ----------------
__device__ __forceinline__ unsigned smem_u32(const void* p) {
    unsigned a;
    asm("{ .reg .u64 t; cvta.to.shared.u64 t, %1; cvt.u32.u64 %0, t; }" : "=r"(a) : "l"(p));
    return a;
}
__device__ __forceinline__ uint4 ldsm_x4(unsigned addr) {
    uint4 r;
    asm volatile("ldmatrix.sync.aligned.m8n8.x4.shared.b16 {%0,%1,%2,%3}, [%4];"
                 : "=r"(r.x), "=r"(r.y), "=r"(r.z), "=r"(r.w) : "r"(addr));
    return r;
}
__device__ __forceinline__ void mma_bf16(float* c, uint4 a, unsigned b0, unsigned b1) {
    asm volatile(
        "mma.sync.aligned.m16n8k16.row.col.f32.bf16.bf16.f32 "
        "{%0,%1,%2,%3}, {%4,%5,%6,%7}, {%8,%9}, {%0,%1,%2,%3};"
        : "+f"(c[0]), "+f"(c[1]), "+f"(c[2]), "+f"(c[3])
        : "r"(a.x), "r"(a.y), "r"(a.z), "r"(a.w), "r"(b0), "r"(b1));
}
__device__ __forceinline__ unsigned pack_bf16x2(float f0, float f1) {
    unsigned r;
    asm("cvt.rn.bf16x2.f32 %0, %1, %2;" : "=r"(r) : "f"(f1), "f"(f0));
    return r;
}
__device__ __forceinline__ void cp_async16(unsigned sdst, const void* gsrc) {
    unsigned long long g;
    asm("cvta.to.global.u64 %0, %1;" : "=l"(g) : "l"(gsrc));
    asm volatile("cp.async.cg.shared.global [%0], [%1], 16;" :: "r"(sdst), "l"(g) : "memory");
}
#define CP_COMMIT() asm volatile("cp.async.commit_group;" ::: "memory")
#define CP_WAIT0()  asm volatile("cp.async.wait_group 0;" ::: "memory")
#define CP_WAIT1()  asm volatile("cp.async.wait_group 1;" ::: "memory")

// rational tanh, 4 at a time, one Newton-refined RCP
__device__ __forceinline__ void tanh4(const float* x, float* y) {
    float al[4], be[4];
#pragma unroll
    for (int i = 0; i < 4; i++) {
        float xc = fminf(fmaxf(x[i], -7.90531110763549805f), 7.90531110763549805f);
        float t = xc * xc;
        float a = -2.76076847742355e-16f;
        a = fmaf(a, t, 2.00018790482477e-13f);
        a = fmaf(a, t, -8.60467152213735e-11f);
        a = fmaf(a, t, 5.12229709037114e-08f);
        a = fmaf(a, t, 1.48572235717979e-05f);
        a = fmaf(a, t, 6.37261928875436e-04f);
        a = fmaf(a, t, 4.89352455891786e-03f);
        al[i] = xc * a;
        float b = 1.19825839466702e-06f;
        b = fmaf(b, t, 1.18534705686654e-04f);
        b = fmaf(b, t, 2.26843463243900e-03f);
        be[i] = fmaf(b, t, 4.89352518554385e-03f);
    }
    float p01 = be[0] * be[1];
    float p23 = be[2] * be[3];
    float p = p01 * p23;
    float r;
    asm("rcp.approx.f32 %0, %1;" : "=f"(r) : "f"(p));
    r = r * fmaf(-p, r, 2.0f);
    float q01 = r * p23, q23 = r * p01;
    y[0] = al[0] * (q01 * be[1]);
    y[1] = al[1] * (q01 * be[0]);
    y[2] = al[2] * (q23 * be[3]);
    y[3] = al[3] * (q23 * be[2]);
}

// ---------------- fused prep kernel ----------------
#define PREP_ENC_BLKS   65536
#define PREP_W2_BLKS    1024
#define PREP_T1_BLKS    4096
#define PREP_INIT_BLKS  256
#define PREP_GRID (PREP_ENC_BLKS + PREP_W2_BLKS + PREP_T1_BLKS + PREP_INIT_BLKS)

__global__ void k_prep(const float4* __restrict__ enc4,
                       const float* __restrict__ attn_w,
                       const float* __restrict__ attn_b,
                       const float* __restrict__ hidden,
                       float* __restrict__ ctx) {
    int blk = blockIdx.x;
    int tid = threadIdx.x;
    if (blk < PREP_ENC_BLKS) {
        int i = blk * 256 + tid;
        float4 x = enc4[i];
        float hx = __bfloat162float(__float2bfloat16(x.x));
        float hy = __bfloat162float(__float2bfloat16(x.y));
        float hz = __bfloat162float(__float2bfloat16(x.z));
        float hw = __bfloat162float(__float2bfloat16(x.w));
        ((uint2*)g_enc_hi)[i] = make_uint2(pack_bf16x2(x.x, x.y), pack_bf16x2(x.z, x.w));
        ((uint2*)g_enc_lo)[i] = make_uint2(pack_bf16x2(x.x - hx, x.y - hy),
                                           pack_bf16x2(x.z - hz, x.w - hw));
    } else if (blk < PREP_ENC_BLKS + PREP_W2_BLKS) {
        int i = (blk - PREP_ENC_BLKS) * 256 + tid;
        int row = i >> 8, c4 = i & 255;
        float4 x = *(const float4*)(attn_w + (size_t)row * (2 * H_DIM) + H_DIM + c4 * 4);
        float hx = __bfloat162float(__float2bfloat16(x.x));
        float hy = __bfloat162float(__float2bfloat16(x.y));
        float hz = __bfloat162float(__float2bfloat16(x.z));
        float hw = __bfloat162float(__float2bfloat16(x.w));
        ((uint2*)g_w2_hi)[i] = make_uint2(pack_bf16x2(x.x, x.y), pack_bf16x2(x.z, x.w));
        ((uint2*)g_w2_lo)[i] = make_uint2(pack_bf16x2(x.x - hx, x.y - hy),
                                          pack_bf16x2(x.z - hz, x.w - hw));
    } else if (blk < PREP_ENC_BLKS + PREP_W2_BLKS + PREP_T1_BLKS) {
        int w = (blk - PREP_ENC_BLKS - PREP_W2_BLKS) * 8 + (tid >> 5);
        int lane = tid & 31;
        int b = w >> 10;
        int h = w & (H_DIM - 1);
        const float4* hp = (const float4*)(hidden + (size_t)b * H_DIM);
        const float4* wp = (const float4*)(attn_w + (size_t)h * 2 * H_DIM);
        float acc = 0.f;
#pragma unroll
        for (int i = 0; i < 8; i++) {
            int idx = i * 32 + lane;
            float4 hv = hp[idx];
            float4 wv = wp[idx];
            acc += hv.x * wv.x + hv.y * wv.y + hv.z * wv.z + hv.w * wv.w;
        }
#pragma unroll
        for (int off = 16; off; off >>= 1) acc += __shfl_down_sync(0xffffffffu, acc, off);
        if (lane == 0) g_t1[w] = acc + attn_b[h];
    } else {
        int i = (blk - PREP_ENC_BLKS - PREP_W2_BLKS - PREP_T1_BLKS) * 256 + tid;
        if (i < B_DIM * S_LEN) g_scores[i] = 0.f;
        if (i < B_DIM * H_DIM) ctx[i] = 0.f;
    }
}

// ---------------- K1: 128x128 CTA (4 warps), 2 CTAs/SM, 3-stage cp.async ----------------
#define BM 128
#define BN 128
#define BK 32
#define A_HI 0
#define A_LO 8192
#define B_HI 16384
#define B_LO 24576
#define STAGE_B 32768
#define NSTAGE 3
#define VS_OFF  (NSTAGE * STAGE_B)          // 98304: 128 f32
#define SROW_OFF (VS_OFF + 512)             // 98816: 128 f32
#define K1_SMEM  (SROW_OFF + 512)           // 99328

__device__ __forceinline__ unsigned sw_off(int row, int c16) {
    return (unsigned)row * 64u + (unsigned)((c16 ^ ((row >> 1) & 3)) << 4);
}

__device__ __forceinline__ void fill_stage(unsigned sb, int m0, int n0, int kk, int tid) {
#pragma unroll
    for (int i = 0; i < 4; i++) {
        int idx = i * 128 + tid;
        int row = idx >> 2, c16 = idx & 3;
        size_t goff = (size_t)(m0 + row) * H_DIM + kk + c16 * 8;
        unsigned soff = sw_off(row, c16);
        cp_async16(sb + A_HI + soff, g_enc_hi + goff);
        cp_async16(sb + A_LO + soff, g_enc_lo + goff);
    }
#pragma unroll
    for (int i = 0; i < 4; i++) {
        int idx = i * 128 + tid;
        int row = idx >> 2, c16 = idx & 3;
        size_t goff = (size_t)(n0 + row) * H_DIM + kk + c16 * 8;
        unsigned soff = sw_off(row, c16);
        cp_async16(sb + B_HI + soff, g_w2_hi + goff);
        cp_async16(sb + B_LO + soff, g_w2_lo + goff);
    }
}

__global__ void __launch_bounds__(128, 2) k1_gemm(const float* __restrict__ v) {
    extern __shared__ char smem[];
    const unsigned sbase = smem_u32(smem);
    const int tid = threadIdx.x;
    const int wid = tid >> 5;
    const int L = tid & 31;
    const int wm = wid & 1;
    const int wn = wid >> 1;
    const int m0 = blockIdx.y * BM;
    const int n0 = blockIdx.x * BN;

    float* vs = (float*)(smem + VS_OFF);
    float* srow = (float*)(smem + SROW_OFF);
    vs[tid] = v[n0 + tid];
    srow[tid] = 0.f;

    fill_stage(sbase, m0, n0, 0, tid);
    CP_COMMIT();
    fill_stage(sbase + STAGE_B, m0, n0, BK, tid);
    CP_COMMIT();

    float acc[4][8][4];
#pragma unroll
    for (int i = 0; i < 4; i++)
#pragma unroll
        for (int j = 0; j < 8; j++)
#pragma unroll
            for (int e = 0; e < 4; e++) acc[i][j][e] = 0.f;

    const int a_r = wm * 64 + ((L >> 3) & 1) * 8 + (L & 7);
    const int a_c = (L >> 4);
    const int b_r = wn * 64 + (L >> 4) * 8 + (L & 7);
    const int b_c = ((L >> 3) & 1);

    const int NKT = H_DIM / BK;              // 32
    int slot = 0, nslot = 2;
    for (int kt = 0; kt < NKT; kt++) {
        if (kt + 1 < NKT) { CP_WAIT1(); } else { CP_WAIT0(); }
        __syncthreads();
        if (kt + 2 < NKT) {
            fill_stage(sbase + nslot * STAGE_B, m0, n0, (kt + 2) * BK, tid);
            CP_COMMIT();
        }
        const unsigned sb = sbase + slot * STAGE_B;
#pragma unroll
        for (int ks = 0; ks < 2; ks++) {
            uint4 ah[4], al[4], bh[4], bl[4];
#pragma unroll
            for (int mf = 0; mf < 4; mf++) {
                int row = a_r + mf * 16;
                unsigned off = sw_off(row, ks * 2 + a_c);
                ah[mf] = ldsm_x4(sb + A_HI + off);
                al[mf] = ldsm_x4(sb + A_LO + off);
            }
#pragma unroll
            for (int nf2 = 0; nf2 < 4; nf2++) {
                int row = b_r + nf2 * 16;
                unsigned off = sw_off(row, ks * 2 + b_c);
                bh[nf2] = ldsm_x4(sb + B_HI + off);
                bl[nf2] = ldsm_x4(sb + B_LO + off);
            }
#pragma unroll
            for (int mf = 0; mf < 4; mf++)
#pragma unroll
                for (int nf2 = 0; nf2 < 4; nf2++) {
                    mma_bf16(acc[mf][nf2 * 2],     ah[mf], bh[nf2].x, bh[nf2].y);
                    mma_bf16(acc[mf][nf2 * 2 + 1], ah[mf], bh[nf2].z, bh[nf2].w);
                }
#pragma unroll
            for (int mf = 0; mf < 4; mf++)
#pragma unroll
                for (int nf2 = 0; nf2 < 4; nf2++) {
                    mma_bf16(acc[mf][nf2 * 2],     ah[mf], bl[nf2].x, bl[nf2].y);
                    mma_bf16(acc[mf][nf2 * 2 + 1], ah[mf], bl[nf2].z, bl[nf2].w);
                }
#pragma unroll
            for (int mf = 0; mf < 4; mf++)
#pragma unroll
                for (int nf2 = 0; nf2 < 4; nf2++) {
                    mma_bf16(acc[mf][nf2 * 2],     al[mf], bh[nf2].x, bh[nf2].y);
                    mma_bf16(acc[mf][nf2 * 2 + 1], al[mf], bh[nf2].z, bh[nf2].w);
                }
        }
        slot = (slot == 2) ? 0 : slot + 1;
        nslot = (nslot == 2) ? 0 : nslot + 1;
    }

    // ---------------- epilogue: batched t1 loads + tanh + v-dot + row reduce ----------------
    const int q = L >> 2;
#pragma unroll
    for (int mf = 0; mf < 4; mf++) {
        const int r0 = m0 + wm * 64 + mf * 16 + q;
        const int bb0 = r0 & 31;
        const int bb1 = (r0 + 8) & 31;
        float2 t0a[8], t1a[8];
#pragma unroll
        for (int nf = 0; nf < 8; nf++) {
            const int c = n0 + wn * 64 + nf * 8 + (L & 3) * 2;
            t0a[nf] = __ldg((const float2*)(g_t1 + (size_t)bb0 * H_DIM + c));
            t1a[nf] = __ldg((const float2*)(g_t1 + (size_t)bb1 * H_DIM + c));
        }
        float rp0 = 0.f, rp1 = 0.f;
#pragma unroll
        for (int nf = 0; nf < 8; nf++) {
            const int cl = wn * 64 + nf * 8 + (L & 3) * 2;
            float x[4], y[4];
            x[0] = acc[mf][nf][0] + t0a[nf].x;
            x[1] = acc[mf][nf][1] + t0a[nf].y;
            x[2] = acc[mf][nf][2] + t1a[nf].x;
            x[3] = acc[mf][nf][3] + t1a[nf].y;
            tanh4(x, y);
            rp0 += y[0] * vs[cl] + y[1] * vs[cl + 1];
            rp1 += y[2] * vs[cl] + y[3] * vs[cl + 1];
        }
        rp0 += __shfl_xor_sync(0xffffffffu, rp0, 1);
        rp0 += __shfl_xor_sync(0xffffffffu, rp0, 2);
        rp1 += __shfl_xor_sync(0xffffffffu, rp1, 1);
        rp1 += __shfl_xor_sync(0xffffffffu, rp1, 2);
        if ((L & 3) == 0) {
            atomicAdd(&srow[wm * 64 + mf * 16 + q], rp0);
            atomicAdd(&srow[wm * 64 + mf * 16 + q + 8], rp1);
        }
    }
    __syncthreads();
    {
        int rowg = m0 + tid;
        atomicAdd(&g_scores[(rowg & 31) * S_LEN + (rowg >> 5)], srow[tid]);
    }
}

// ---------------- fused softmax + context ----------------
// grid (NCHUNK, B); each CTA computes softmax stats for its b (redundant),
// writes its weight slice, accumulates its context chunk.
#define NCHUNK 64
#define CHUNK_S (S_LEN / NCHUNK)     // 32

__global__ void k23_softmax_context(const float* __restrict__ enc,
                                    const int* __restrict__ lens,
                                    float* __restrict__ wout,
                                    float* __restrict__ ctx) {
    __shared__ float red[256];
    __shared__ float wsh[CHUNK_S];
    int b = blockIdx.y;
    int len = lens[b];
    int s0 = blockIdx.x * CHUNK_S;
    const float* sc = g_scores + (size_t)b * S_LEN;
    int tid = threadIdx.x;

    // max over [0, len)
    float mx = -3.4e38f;
    for (int s = tid; s < len; s += 256) mx = fmaxf(mx, sc[s]);
    red[tid] = mx;
    __syncthreads();
    for (int off = 128; off; off >>= 1) {
        if (tid < off) red[tid] = fmaxf(red[tid], red[tid + off]);
        __syncthreads();
    }
    mx = red[0];
    __syncthreads();

    // sum of exp
    float sum = 0.f;
    for (int s = tid; s < len; s += 256) sum += expf(sc[s] - mx);
    red[tid] = sum;
    __syncthreads();
    for (int off = 128; off; off >>= 1) {
        if (tid < off) red[tid] += red[tid + off];
        __syncthreads();
    }
    float inv = 1.f / red[0];

    // weights for this chunk
    if (tid < CHUNK_S) {
        int s = s0 + tid;
        float w = (s < len) ? expf(sc[s] - mx) * inv : 0.f;
        wsh[tid] = w;
        wout[(size_t)b * S_LEN + s] = w;
    }
    __syncthreads();

    // context accumulation over this chunk
    int s1 = min(s0 + CHUNK_S, len);
    if (s0 >= s1) return;
    int h = tid * 4;
    float4 acc = make_float4(0.f, 0.f, 0.f, 0.f);
    for (int s = s0; s < s1; s++) {
        float w = wsh[s - s0];
        float4 e = *(const float4*)(enc + ((size_t)(s * B_DIM + b)) * H_DIM + h);
        acc.x += w * e.x; acc.y += w * e.y; acc.z += w * e.z; acc.w += w * e.w;
    }
    float* c = ctx + (size_t)b * H_DIM + h;
    atomicAdd(c + 0, acc.x);
    atomicAdd(c + 1, acc.y);
    atomicAdd(c + 2, acc.z);
    atomicAdd(c + 3, acc.w);
}

// ---------------- launcher ----------------
extern "C" void kernel_launch(void* const* d_in, const int* in_sizes, int n_in,
                              void* d_out, int out_size) {
    const float* hidden = (const float*)d_in[0];
    const float* enc    = (const float*)d_in[1];
    const int*   lens   = (const int*)d_in[2];
    const float* attn_w = (const float*)d_in[3];
    const float* attn_b = (const float*)d_in[4];
    const float* v      = (const float*)d_in[5];

    float* out = (float*)d_out;
    float* ctx = out;
    float* wts = out + B_DIM * H_DIM;

    cudaFuncSetAttribute(k1_gemm, cudaFuncAttributeMaxDynamicSharedMemorySize, K1_SMEM);

    k_prep<<<PREP_GRID, 256>>>((const float4*)enc, attn_w, attn_b, hidden, ctx);
    dim3 g1(H_DIM / BN, M_TOT / BM);     // (8, 512), n fastest -> A reuse in L2
    k1_gemm<<<g1, 128, K1_SMEM>>>(v);
    dim3 g23(NCHUNK, B_DIM);
    k23_softmax_context<<<g23, 256>>>(enc, lens, wts, ctx);
}

// round 10
// speedup vs baseline: 1.0672x; 1.0245x over previous
#include <cuda_runtime.h>
#include <cuda_bf16.h>

#define S_LEN 2048
#define B_DIM 32
#define H_DIM 1024
#define M_TOT (S_LEN * B_DIM)

// ---------------- scratch ----------------
__device__ __nv_bfloat16 g_enc_hi[(size_t)M_TOT * H_DIM];   // 128 MB
__device__ __nv_bfloat16 g_enc_lo[(size_t)M_TOT * H_DIM];   // 128 MB
__device__ __nv_bfloat16 g_w2_hi[H_DIM * H_DIM];
__device__ __nv_bfloat16 g_w2_lo[H_DIM * H_DIM];
__device__ float g_t1[B_DIM * H_DIM];
__device__ float g_scores[B_DIM * S_LEN];

// ---------------- helpers ----------------
__device__ __forceinline__ unsigned smem_u32(const void* p) {
    unsigned a;
    asm("{ .reg .u64 t; cvta.to.shared.u64 t, %1; cvt.u32.u64 %0, t; }" : "=r"(a) : "l"(p));
    return a;
}
__device__ __forceinline__ uint4 ldsm_x4(unsigned addr) {
    uint4 r;
    asm volatile("ldmatrix.sync.aligned.m8n8.x4.shared.b16 {%0,%1,%2,%3}, [%4];"
                 : "=r"(r.x), "=r"(r.y), "=r"(r.z), "=r"(r.w) : "r"(addr));
    return r;
}
__device__ __forceinline__ void mma_bf16(float* c, uint4 a, unsigned b0, unsigned b1) {
    asm volatile(
        "mma.sync.aligned.m16n8k16.row.col.f32.bf16.bf16.f32 "
        "{%0,%1,%2,%3}, {%4,%5,%6,%7}, {%8,%9}, {%0,%1,%2,%3};"
        : "+f"(c[0]), "+f"(c[1]), "+f"(c[2]), "+f"(c[3])
        : "r"(a.x), "r"(a.y), "r"(a.z), "r"(a.w), "r"(b0), "r"(b1));
}
__device__ __forceinline__ unsigned pack_bf16x2(float f0, float f1) {
    unsigned r;
    asm("cvt.rn.bf16x2.f32 %0, %1, %2;" : "=r"(r) : "f"(f1), "f"(f0));
    return r;
}
__device__ __forceinline__ void cp_async16(unsigned sdst, const void* gsrc) {
    unsigned long long g;
    asm("cvta.to.global.u64 %0, %1;" : "=l"(g) : "l"(gsrc));
    asm volatile("cp.async.cg.shared.global [%0], [%1], 16;" :: "r"(sdst), "l"(g) : "memory");
}
#define CP_COMMIT() asm volatile("cp.async.commit_group;" ::: "memory")
#define CP_WAIT0()  asm volatile("cp.async.wait_group 0;" ::: "memory")
#define CP_WAIT1()  asm volatile("cp.async.wait_group 1;" ::: "memory")

// rational tanh, 4 at a time, one Newton-refined RCP
__device__ __forceinline__ void tanh4(const float* x, float* y) {
    float al[4], be[4];
#pragma unroll
    for (int i = 0; i < 4; i++) {
        float xc = fminf(fmaxf(x[i], -7.90531110763549805f), 7.90531110763549805f);
        float t = xc * xc;
        float a = -2.76076847742355e-16f;
        a = fmaf(a, t, 2.00018790482477e-13f);
        a = fmaf(a, t, -8.60467152213735e-11f);
        a = fmaf(a, t, 5.12229709037114e-08f);
        a = fmaf(a, t, 1.48572235717979e-05f);
        a = fmaf(a, t, 6.37261928875436e-04f);
        a = fmaf(a, t, 4.89352455891786e-03f);
        al[i] = xc * a;
        float b = 1.19825839466702e-06f;
        b = fmaf(b, t, 1.18534705686654e-04f);
        b = fmaf(b, t, 2.26843463243900e-03f);
        be[i] = fmaf(b, t, 4.89352518554385e-03f);
    }
    float p01 = be[0] * be[1];
    float p23 = be[2] * be[3];
    float p = p01 * p23;
    float r;
    asm("rcp.approx.f32 %0, %1;" : "=f"(r) : "f"(p));
    r = r * fmaf(-p, r, 2.0f);
    float q01 = r * p23, q23 = r * p01;
    y[0] = al[0] * (q01 * be[1]);
    y[1] = al[1] * (q01 * be[0]);
    y[2] = al[2] * (q23 * be[3]);
    y[3] = al[3] * (q23 * be[2]);
}

// ---------------- fused prep kernel ----------------
// enc: each thread handles 4 consecutive float4s (MLP=4, STG.128 stores)
#define PREP_ENC_BLKS   16384
#define PREP_W2_BLKS    1024
#define PREP_T1_BLKS    4096
#define PREP_INIT_BLKS  256
#define PREP_GRID (PREP_ENC_BLKS + PREP_W2_BLKS + PREP_T1_BLKS + PREP_INIT_BLKS)

__global__ void k_prep(const float4* __restrict__ enc4,
                       const float* __restrict__ attn_w,
                       const float* __restrict__ attn_b,
                       const float* __restrict__ hidden,
                       float* __restrict__ ctx) {
    int blk = blockIdx.x;
    int tid = threadIdx.x;
    if (blk < PREP_ENC_BLKS) {
        // 16 floats per thread: 4 x LDG.128 batched, 2+2 x STG.128
        size_t i0 = ((size_t)blk * 256 + tid) * 4;     // float4 index
        float4 x[4];
#pragma unroll
        for (int i = 0; i < 4; i++) x[i] = enc4[i0 + i];
        unsigned hi[8], lo[8];
#pragma unroll
        for (int i = 0; i < 4; i++) {
            float hx = __bfloat162float(__float2bfloat16(x[i].x));
            float hy = __bfloat162float(__float2bfloat16(x[i].y));
            float hz = __bfloat162float(__float2bfloat16(x[i].z));
            float hw = __bfloat162float(__float2bfloat16(x[i].w));
            hi[i * 2]     = pack_bf16x2(x[i].x, x[i].y);
            hi[i * 2 + 1] = pack_bf16x2(x[i].z, x[i].w);
            lo[i * 2]     = pack_bf16x2(x[i].x - hx, x[i].y - hy);
            lo[i * 2 + 1] = pack_bf16x2(x[i].z - hz, x[i].w - hw);
        }
        uint4* dh = (uint4*)(g_enc_hi + i0 * 4);       // i0*4 bf16 elements
        uint4* dl = (uint4*)(g_enc_lo + i0 * 4);
        dh[0] = make_uint4(hi[0], hi[1], hi[2], hi[3]);
        dh[1] = make_uint4(hi[4], hi[5], hi[6], hi[7]);
        dl[0] = make_uint4(lo[0], lo[1], lo[2], lo[3]);
        dl[1] = make_uint4(lo[4], lo[5], lo[6], lo[7]);
    } else if (blk < PREP_ENC_BLKS + PREP_W2_BLKS) {
        int i = (blk - PREP_ENC_BLKS) * 256 + tid;
        int row = i >> 8, c4 = i & 255;
        float4 x = *(const float4*)(attn_w + (size_t)row * (2 * H_DIM) + H_DIM + c4 * 4);
        float hx = __bfloat162float(__float2bfloat16(x.x));
        float hy = __bfloat162float(__float2bfloat16(x.y));
        float hz = __bfloat162float(__float2bfloat16(x.z));
        float hw = __bfloat162float(__float2bfloat16(x.w));
        ((uint2*)g_w2_hi)[i] = make_uint2(pack_bf16x2(x.x, x.y), pack_bf16x2(x.z, x.w));
        ((uint2*)g_w2_lo)[i] = make_uint2(pack_bf16x2(x.x - hx, x.y - hy),
                                          pack_bf16x2(x.z - hz, x.w - hw));
    } else if (blk < PREP_ENC_BLKS + PREP_W2_BLKS + PREP_T1_BLKS) {
        int w = (blk - PREP_ENC_BLKS - PREP_W2_BLKS) * 8 + (tid >> 5);
        int lane = tid & 31;
        int b = w >> 10;
        int h = w & (H_DIM - 1);
        const float4* hp = (const float4*)(hidden + (size_t)b * H_DIM);
        const float4* wp = (const float4*)(attn_w + (size_t)h * 2 * H_DIM);
        float acc = 0.f;
#pragma unroll
        for (int i = 0; i < 8; i++) {
            int idx = i * 32 + lane;
            float4 hv = hp[idx];
            float4 wv = wp[idx];
            acc += hv.x * wv.x + hv.y * wv.y + hv.z * wv.z + hv.w * wv.w;
        }
#pragma unroll
        for (int off = 16; off; off >>= 1) acc += __shfl_down_sync(0xffffffffu, acc, off);
        if (lane == 0) g_t1[w] = acc + attn_b[h];
    } else {
        int i = (blk - PREP_ENC_BLKS - PREP_W2_BLKS - PREP_T1_BLKS) * 256 + tid;
        if (i < B_DIM * S_LEN) g_scores[i] = 0.f;
        if (i < B_DIM * H_DIM) ctx[i] = 0.f;
    }
}

// ---------------- K1: 128x128 CTA (4 warps), 2 CTAs/SM, 3-stage cp.async ----------------
#define BM 128
#define BN 128
#define BK 32
#define A_HI 0
#define A_LO 8192
#define B_HI 16384
#define B_LO 24576
#define STAGE_B 32768
#define NSTAGE 3
#define VS_OFF  (NSTAGE * STAGE_B)          // 98304: 128 f32
#define SROW_OFF (VS_OFF + 512)             // 98816: 128 f32
#define K1_SMEM  (SROW_OFF + 512)           // 99328

__device__ __forceinline__ unsigned sw_off(int row, int c16) {
    return (unsigned)row * 64u + (unsigned)((c16 ^ ((row >> 1) & 3)) << 4);
}

__device__ __forceinline__ void fill_stage(unsigned sb, int m0, int n0, int kk, int tid) {
#pragma unroll
    for (int i = 0; i < 4; i++) {
        int idx = i * 128 + tid;
        int row = idx >> 2, c16 = idx & 3;
        size_t goff = (size_t)(m0 + row) * H_DIM + kk + c16 * 8;
        unsigned soff = sw_off(row, c16);
        cp_async16(sb + A_HI + soff, g_enc_hi + goff);
        cp_async16(sb + A_LO + soff, g_enc_lo + goff);
    }
#pragma unroll
    for (int i = 0; i < 4; i++) {
        int idx = i * 128 + tid;
        int row = idx >> 2, c16 = idx & 3;
        size_t goff = (size_t)(n0 + row) * H_DIM + kk + c16 * 8;
        unsigned soff = sw_off(row, c16);
        cp_async16(sb + B_HI + soff, g_w2_hi + goff);
        cp_async16(sb + B_LO + soff, g_w2_lo + goff);
    }
}

__global__ void __launch_bounds__(128, 2) k1_gemm(const float* __restrict__ v) {
    extern __shared__ char smem[];
    const unsigned sbase = smem_u32(smem);
    const int tid = threadIdx.x;
    const int wid = tid >> 5;
    const int L = tid & 31;
    const int wm = wid & 1;
    const int wn = wid >> 1;
    const int m0 = blockIdx.y * BM;
    const int n0 = blockIdx.x * BN;

    float* vs = (float*)(smem + VS_OFF);
    float* srow = (float*)(smem + SROW_OFF);
    vs[tid] = v[n0 + tid];
    srow[tid] = 0.f;

    fill_stage(sbase, m0, n0, 0, tid);
    CP_COMMIT();
    fill_stage(sbase + STAGE_B, m0, n0, BK, tid);
    CP_COMMIT();

    float acc[4][8][4];
#pragma unroll
    for (int i = 0; i < 4; i++)
#pragma unroll
        for (int j = 0; j < 8; j++)
#pragma unroll
            for (int e = 0; e < 4; e++) acc[i][j][e] = 0.f;

    const int a_r = wm * 64 + ((L >> 3) & 1) * 8 + (L & 7);
    const int a_c = (L >> 4);
    const int b_r = wn * 64 + (L >> 4) * 8 + (L & 7);
    const int b_c = ((L >> 3) & 1);

    const int NKT = H_DIM / BK;              // 32
    int slot = 0, nslot = 2;
    for (int kt = 0; kt < NKT; kt++) {
        if (kt + 1 < NKT) { CP_WAIT1(); } else { CP_WAIT0(); }
        __syncthreads();
        if (kt + 2 < NKT) {
            fill_stage(sbase + nslot * STAGE_B, m0, n0, (kt + 2) * BK, tid);
            CP_COMMIT();
        }
        const unsigned sb = sbase + slot * STAGE_B;
#pragma unroll
        for (int ks = 0; ks < 2; ks++) {
            uint4 ah[4], al[4], bh[4], bl[4];
#pragma unroll
            for (int mf = 0; mf < 4; mf++) {
                int row = a_r + mf * 16;
                unsigned off = sw_off(row, ks * 2 + a_c);
                ah[mf] = ldsm_x4(sb + A_HI + off);
                al[mf] = ldsm_x4(sb + A_LO + off);
            }
#pragma unroll
            for (int nf2 = 0; nf2 < 4; nf2++) {
                int row = b_r + nf2 * 16;
                unsigned off = sw_off(row, ks * 2 + b_c);
                bh[nf2] = ldsm_x4(sb + B_HI + off);
                bl[nf2] = ldsm_x4(sb + B_LO + off);
            }
#pragma unroll
            for (int mf = 0; mf < 4; mf++)
#pragma unroll
                for (int nf2 = 0; nf2 < 4; nf2++) {
                    mma_bf16(acc[mf][nf2 * 2],     ah[mf], bh[nf2].x, bh[nf2].y);
                    mma_bf16(acc[mf][nf2 * 2 + 1], ah[mf], bh[nf2].z, bh[nf2].w);
                }
#pragma unroll
            for (int mf = 0; mf < 4; mf++)
#pragma unroll
                for (int nf2 = 0; nf2 < 4; nf2++) {
                    mma_bf16(acc[mf][nf2 * 2],     ah[mf], bl[nf2].x, bl[nf2].y);
                    mma_bf16(acc[mf][nf2 * 2 + 1], ah[mf], bl[nf2].z, bl[nf2].w);
                }
#pragma unroll
            for (int mf = 0; mf < 4; mf++)
#pragma unroll
                for (int nf2 = 0; nf2 < 4; nf2++) {
                    mma_bf16(acc[mf][nf2 * 2],     al[mf], bh[nf2].x, bh[nf2].y);
                    mma_bf16(acc[mf][nf2 * 2 + 1], al[mf], bh[nf2].z, bh[nf2].w);
                }
        }
        slot = (slot == 2) ? 0 : slot + 1;
        nslot = (nslot == 2) ? 0 : nslot + 1;
    }

    // ---------------- epilogue: batched t1 loads + tanh + v-dot + row reduce ----------------
    const int q = L >> 2;
#pragma unroll
    for (int mf = 0; mf < 4; mf++) {
        const int r0 = m0 + wm * 64 + mf * 16 + q;
        const int bb0 = r0 & 31;
        const int bb1 = (r0 + 8) & 31;
        float2 t0a[8], t1a[8];
#pragma unroll
        for (int nf = 0; nf < 8; nf++) {
            const int c = n0 + wn * 64 + nf * 8 + (L & 3) * 2;
            t0a[nf] = __ldg((const float2*)(g_t1 + (size_t)bb0 * H_DIM + c));
            t1a[nf] = __ldg((const float2*)(g_t1 + (size_t)bb1 * H_DIM + c));
        }
        float rp0 = 0.f, rp1 = 0.f;
#pragma unroll
        for (int nf = 0; nf < 8; nf++) {
            const int cl = wn * 64 + nf * 8 + (L & 3) * 2;
            float x[4], y[4];
            x[0] = acc[mf][nf][0] + t0a[nf].x;
            x[1] = acc[mf][nf][1] + t0a[nf].y;
            x[2] = acc[mf][nf][2] + t1a[nf].x;
            x[3] = acc[mf][nf][3] + t1a[nf].y;
            tanh4(x, y);
            rp0 += y[0] * vs[cl] + y[1] * vs[cl + 1];
            rp1 += y[2] * vs[cl] + y[3] * vs[cl + 1];
        }
        rp0 += __shfl_xor_sync(0xffffffffu, rp0, 1);
        rp0 += __shfl_xor_sync(0xffffffffu, rp0, 2);
        rp1 += __shfl_xor_sync(0xffffffffu, rp1, 1);
        rp1 += __shfl_xor_sync(0xffffffffu, rp1, 2);
        if ((L & 3) == 0) {
            atomicAdd(&srow[wm * 64 + mf * 16 + q], rp0);
            atomicAdd(&srow[wm * 64 + mf * 16 + q + 8], rp1);
        }
    }
    __syncthreads();
    {
        int rowg = m0 + tid;
        atomicAdd(&g_scores[(rowg & 31) * S_LEN + (rowg >> 5)], srow[tid]);
    }
}

// ---------------- softmax ----------------
__global__ void k2_softmax(const int* __restrict__ lens, float* __restrict__ wout) {
    __shared__ float red[256];
    int b = blockIdx.x;
    int len = lens[b];
    const float* sc = g_scores + (size_t)b * S_LEN;
    int tid = threadIdx.x;

    float mx = -3.4e38f;
    for (int s = tid; s < len; s += 256) mx = fmaxf(mx, sc[s]);
    red[tid] = mx;
    __syncthreads();
    for (int off = 128; off; off >>= 1) {
        if (tid < off) red[tid] = fmaxf(red[tid], red[tid + off]);
        __syncthreads();
    }
    mx = red[0];
    __syncthreads();

    float sum = 0.f;
    for (int s = tid; s < len; s += 256) sum += expf(sc[s] - mx);
    red[tid] = sum;
    __syncthreads();
    for (int off = 128; off; off >>= 1) {
        if (tid < off) red[tid] += red[tid + off];
        __syncthreads();
    }
    float inv = 1.f / red[0];

    for (int s = tid; s < S_LEN; s += 256)
        wout[(size_t)b * S_LEN + s] = (s < len) ? expf(sc[s] - mx) * inv : 0.f;
}

// ---------------- context ----------------
#define NCHUNK 64
__global__ void k3_context(const float* __restrict__ enc,
                           const float* __restrict__ wts,
                           const int* __restrict__ lens,
                           float* __restrict__ ctx) {
    int b = blockIdx.y;
    int len = lens[b];
    int s0 = blockIdx.x * (S_LEN / NCHUNK);
    int s1 = min(s0 + (S_LEN / NCHUNK), len);
    if (s0 >= s1) return;
    int h = threadIdx.x * 4;
    float4 acc = make_float4(0.f, 0.f, 0.f, 0.f);
    for (int s = s0; s < s1; s++) {
        float w = __ldg(&wts[(size_t)b * S_LEN + s]);
        float4 e = *(const float4*)(enc + ((size_t)(s * B_DIM + b)) * H_DIM + h);
        acc.x += w * e.x; acc.y += w * e.y; acc.z += w * e.z; acc.w += w * e.w;
    }
    float* c = ctx + (size_t)b * H_DIM + h;
    atomicAdd(c + 0, acc.x);
    atomicAdd(c + 1, acc.y);
    atomicAdd(c + 2, acc.z);
    atomicAdd(c + 3, acc.w);
}

// ---------------- launcher ----------------
extern "C" void kernel_launch(void* const* d_in, const int* in_sizes, int n_in,
                              void* d_out, int out_size) {
    const float* hidden = (const float*)d_in[0];
    const float* enc    = (const float*)d_in[1];
    const int*   lens   = (const int*)d_in[2];
    const float* attn_w = (const float*)d_in[3];
    const float* attn_b = (const float*)d_in[4];
    const float* v      = (const float*)d_in[5];

    float* out = (float*)d_out;
    float* ctx = out;
    float* wts = out + B_DIM * H_DIM;

    cudaFuncSetAttribute(k1_gemm, cudaFuncAttributeMaxDynamicSharedMemorySize, K1_SMEM);

    k_prep<<<PREP_GRID, 256>>>((const float4*)enc, attn_w, attn_b, hidden, ctx);
    dim3 g1(H_DIM / BN, M_TOT / BM);     // (8, 512), n fastest -> A reuse in L2
    k1_gemm<<<g1, 128, K1_SMEM>>>(v);
    k2_softmax<<<B_DIM, 256>>>(lens, wts);
    dim3 g3(NCHUNK, B_DIM);
    k3_context<<<g3, 256>>>(enc, wts, lens, ctx);
}